// round 15
// baseline (speedup 1.0000x reference)
#include <cuda_runtime.h>
#include <cuda.h>
#include <cstdint>
#include <cstddef>
#include <cstring>

#define D_DIM 64
#define L_DIM 100
#define B_DIM 256
#define H_DIM 10000
#define HC    32                 // h-columns per work item
#define PITCH 32                 // floats per tile row (dense, TMA-packed)
#define DPB   16                 // d's per work item (D split 4 ways)
#define NPART 4
#define NSLICE 313               // ceil(H/HC)
#define NWORK (NSLICE * NPART)   // 1252
#define GRID  296                // 148 SM x occ 2: persistent grid
#define NWHOLE (GRID * 4)        // 1184 items assigned whole
#define NHALF  (NWORK - NWHOLE)  // 68 items split into 136 halves (blocks 0..135)
#define TILE_FLOATS (L_DIM * PITCH)
#define TILE_BYTES  (TILE_FLOATS * 4)       // 12800
#define SCR_BYTES   (B_DIM * 8)             // 2048
#define NBUF  6
#define NTHR  512
#define NWARP (NTHR / 32)

// per-(d,b): {off_lo | off_hi<<16, alpha bits}
__device__ uint2 g_scr2[D_DIM * B_DIM];
// partial sums for D-parts 1..3 (part 0 writes d_out directly)
__device__ float g_part[NPART - 1][B_DIM * H_DIM];

__global__ void __launch_bounds__(256) precomp_kernel(const float* __restrict__ x) {
    int idx = blockIdx.x * 256 + threadIdx.x;
    if (idx >= D_DIM * B_DIM) return;
    int d = idx >> 8;
    int b = idx & 255;
    float xv = x[b * D_DIM + d];
    float xn = fminf(fmaxf(xv * (float)(L_DIM - 1), 0.0f), (float)(L_DIM - 1));
    float fl = floorf(xn);
    int lo = (int)fl;
    int hi = min(lo + 1, L_DIM - 1);
    uint2 r;
    r.x = (uint32_t)(lo * PITCH) | ((uint32_t)(hi * PITCH) << 16);
    r.y = __float_as_uint(xn - fl);
    g_scr2[idx] = r;
}

// ---- Blackwell packed fp32x2 helpers ----
__device__ __forceinline__ unsigned long long pk2(float v) {
    unsigned long long r;
    asm("mov.b64 %0, {%1, %2};" : "=l"(r) : "f"(v), "f"(v));
    return r;
}
__device__ __forceinline__ unsigned long long ffma2(unsigned long long a,
                                                    unsigned long long b,
                                                    unsigned long long c) {
    unsigned long long d;
    asm("fma.rn.f32x2 %0, %1, %2, %3;" : "=l"(d) : "l"(a), "l"(b), "l"(c));
    return d;
}

// ---- mbarrier / TMA helpers ----
__device__ __forceinline__ void mbar_init(uint32_t addr, uint32_t count) {
    asm volatile("mbarrier.init.shared.b64 [%0], %1;" :: "r"(addr), "r"(count) : "memory");
}
__device__ __forceinline__ void mbar_expect_tx(uint32_t addr, uint32_t bytes) {
    asm volatile("mbarrier.arrive.expect_tx.shared.b64 _, [%0], %1;"
                 :: "r"(addr), "r"(bytes) : "memory");
}
__device__ __forceinline__ void mbar_arrive(uint32_t addr) {
    asm volatile("mbarrier.arrive.release.cta.shared::cta.b64 _, [%0];"
                 :: "r"(addr) : "memory");
}
__device__ __forceinline__ void mbar_wait_acq(uint32_t addr, uint32_t parity) {
    asm volatile(
        "{\n\t.reg .pred P;\n"
        "WL_%=:\n\t"
        "mbarrier.try_wait.parity.acquire.cta.shared::cta.b64 P, [%0], %1, 0x989680;\n\t"
        "@!P bra WL_%=;\n\t}"
        :: "r"(addr), "r"(parity) : "memory");
}
__device__ __forceinline__ void tma_load_2d(uint32_t smem_dst, const CUtensorMap* tmap,
                                            int cx, int cy, uint32_t mbar) {
    asm volatile(
        "cp.async.bulk.tensor.2d.shared::cta.global.tile.mbarrier::complete_tx::bytes "
        "[%0], [%1, {%2, %3}], [%4];"
        :: "r"(smem_dst), "l"(tmap), "r"(cx), "r"(cy), "r"(mbar) : "memory");
}
__device__ __forceinline__ void bulk_copy_g2s(uint32_t smem_dst, const void* gsrc,
                                              uint32_t bytes, uint32_t mbar) {
    unsigned long long ga = (unsigned long long)__cvta_generic_to_global(gsrc);
    asm volatile(
        "cp.async.bulk.shared::cta.global.mbarrier::complete_tx::bytes [%0], [%1], %2, [%3];"
        :: "r"(smem_dst), "l"(ga), "r"(bytes), "r"(mbar) : "memory");
}

// item id for local unit wi of block bid (wi<4 whole; wi==4 = half item)
__device__ __forceinline__ int unit_item(int bid, int wi) {
    return (wi < 4) ? (bid + wi * GRID) : (NWHOLE + (bid >> 1));
}

__global__ void __launch_bounds__(NTHR, 2) encode_kernel(
        const __grid_constant__ CUtensorMap tmap,
        float* __restrict__ out) {
    __shared__ float tile[NBUF][TILE_FLOATS];
    __shared__ uint2 sscr[NBUF][B_DIM];
    __shared__ __align__(8) unsigned long long mb_full[NBUF];
    __shared__ __align__(8) unsigned long long mb_empty[NBUF];

    const int tid  = threadIdx.x;
    const int lane = tid & 31;
    const int wrp  = tid >> 5;
    const int hg   = tid & 7;        // which float4 within the 32-column slice
    const int bg   = tid >> 3;       // batch group: 4 batches per thread (0..63)
    const int bid  = blockIdx.x;

    // blocks 0..135 get 4 whole items + 1 half item; blocks 136..295 get 4
    const int nitems  = (bid < NHALF * 2) ? 5 : 4;
    const int nstages = nitems * DPB;
    const int hsel    = bid & 1;     // which batch half for the half item

    if (tid == 0) {
#pragma unroll
        for (int i = 0; i < NBUF; ++i) {
            mbar_init((uint32_t)__cvta_generic_to_shared(&mb_full[i]), 1);
            mbar_init((uint32_t)__cvta_generic_to_shared(&mb_empty[i]), NWARP);
        }
        asm volatile("fence.proxy.async.shared::cta;" ::: "memory");
    }
    __syncthreads();          // the only block-wide barrier

    // producer: issue local stage ls (unit wi = ls/16, t = ls%16)
    auto issue = [&](int ls) {
        int wi = ls >> 4;
        int t  = ls & 15;
        int w  = unit_item(bid, wi);
        int part  = w & 3;
        int slice = w >> 2;
        int d     = part * DPB + t;
        int slot  = ls % NBUF;
        uint32_t bar = (uint32_t)__cvta_generic_to_shared(&mb_full[slot]);
        mbar_expect_tx(bar, TILE_BYTES + SCR_BYTES);
        tma_load_2d((uint32_t)__cvta_generic_to_shared(&tile[slot][0]),
                    &tmap, slice * HC, d * L_DIM, bar);
        bulk_copy_g2s((uint32_t)__cvta_generic_to_shared(&sscr[slot][0]),
                      &g_scr2[d * B_DIM], SCR_BYTES, bar);
    };

    if (tid == 0) {
        int npro = (nstages < NBUF - 1) ? nstages : (NBUF - 1);
        for (int ls = 0; ls < npro; ++ls) issue(ls);
    }

    int ls = 0;
    for (int wi = 0; wi < nitems; ++wi) {
        const int w      = unit_item(bid, wi);
        const int part   = w & 3;
        const int slice  = w >> 2;
        const int h      = slice * HC + hg * 4;
        const bool active = (wi < 4) || ((bg >> 5) == hsel);   // half item: my batch half?
        const bool do_out = active && (h < H_DIM);
        float* dst = (part == 0) ? out : &g_part[part - 1][0];

        unsigned long long acc[4][2];
#pragma unroll
        for (int i = 0; i < 4; ++i) { acc[i][0] = 0ull; acc[i][1] = 0ull; }

        for (int t = 0; t < DPB; ++t, ++ls) {
            const int slot = ls % NBUF;
            mbar_wait_acq((uint32_t)__cvta_generic_to_shared(&mb_full[slot]),
                          (uint32_t)((ls / NBUF) & 1));

            if (active) {
                const float* tb = tile[slot];
                const uint2* sc = &sscr[slot][bg * 4];
#pragma unroll
                for (int i = 0; i < 4; ++i) {
                    uint2 s = sc[i];                // LDS.64 broadcast within 8-lane group
                    int off_lo = (int)(s.x & 0xFFFFu);
                    int off_hi = (int)(s.x >> 16);
                    float a = __uint_as_float(s.y);
                    unsigned long long wa = pk2(a);
                    unsigned long long w0 = pk2(1.0f - a);
                    ulonglong2 vl = *reinterpret_cast<const ulonglong2*>(tb + off_lo + hg * 4);
                    ulonglong2 vh = *reinterpret_cast<const ulonglong2*>(tb + off_hi + hg * 4);
                    acc[i][0] = ffma2(w0, vl.x, acc[i][0]);
                    acc[i][1] = ffma2(w0, vl.y, acc[i][1]);
                    acc[i][0] = ffma2(wa, vh.x, acc[i][0]);
                    acc[i][1] = ffma2(wa, vh.y, acc[i][1]);
                }
            }

            __syncwarp();
            if (lane == 0)
                mbar_arrive((uint32_t)__cvta_generic_to_shared(&mb_empty[slot]));

            // rotating producer: stage ln is issued by warp (ln & 15)
            {
                int ln = ls + NBUF - 1;
                if (ln < nstages && wrp == (ln & 15) && lane == 0) {
                    int j = ln / NBUF;          // reuse index of that slot
                    if (j >= 1)
                        mbar_wait_acq((uint32_t)__cvta_generic_to_shared(&mb_empty[ln % NBUF]),
                                      (uint32_t)((j - 1) & 1));
                    issue(ln);
                }
            }
        }

        if (do_out) {
#pragma unroll
            for (int i = 0; i < 4; ++i) {
                ulonglong2 o;
                o.x = acc[i][0];
                o.y = acc[i][1];
                *reinterpret_cast<ulonglong2*>(dst + (size_t)(bg * 4 + i) * H_DIM + h) = o;
            }
        }
    }
}

#define NCHUNK 10   // ceil(10000 / (256*4))

__global__ void __launch_bounds__(256) normalize_kernel(float* __restrict__ out) {
    int b = blockIdx.x;
    const size_t off = (size_t)b * H_DIM;
    float* row = out + off;
    const float* p0 = &g_part[0][off];
    const float* p1 = &g_part[1][off];
    const float* p2 = &g_part[2][off];

    // combine the four partials once, hold in registers (<=10 float4/thread)
    float4 v[NCHUNK];
    int nv = 0;
    float ss = 0.0f;
    for (int i = threadIdx.x * 4; i < H_DIM; i += 256 * 4, ++nv) {
        float4 t  = *reinterpret_cast<const float4*>(row + i);
        float4 a0 = *reinterpret_cast<const float4*>(p0 + i);
        float4 a1 = *reinterpret_cast<const float4*>(p1 + i);
        float4 a2 = *reinterpret_cast<const float4*>(p2 + i);
        t.x += a0.x + a1.x + a2.x;
        t.y += a0.y + a1.y + a2.y;
        t.z += a0.z + a1.z + a2.z;
        t.w += a0.w + a1.w + a2.w;
        v[nv] = t;
        ss += t.x * t.x + t.y * t.y + t.z * t.z + t.w * t.w;
    }
#pragma unroll
    for (int o = 16; o; o >>= 1) ss += __shfl_down_sync(0xffffffffu, ss, o);

    __shared__ float red[8];
    __shared__ float inv_s;
    if ((threadIdx.x & 31) == 0) red[threadIdx.x >> 5] = ss;
    __syncthreads();
    if (threadIdx.x == 0) {
        float t = 0.0f;
#pragma unroll
        for (int i = 0; i < 8; ++i) t += red[i];
        inv_s = rsqrtf(t);
    }
    __syncthreads();
    float inv = inv_s;

    nv = 0;
    for (int i = threadIdx.x * 4; i < H_DIM; i += 256 * 4, ++nv) {
        float4 t = v[nv];
        t.x *= inv; t.y *= inv; t.z *= inv; t.w *= inv;
        *reinterpret_cast<float4*>(row + i) = t;
    }
}

// ---- host-side tensor-map construction (no -lcuda needed) ----
typedef CUresult (*encode_tiled_fn)(
    CUtensorMap*, CUtensorMapDataType, cuuint32_t, void*,
    const cuuint64_t*, const cuuint64_t*, const cuuint32_t*, const cuuint32_t*,
    CUtensorMapInterleave, CUtensorMapSwizzle, CUtensorMapL2promotion,
    CUtensorMapFloatOOBfill);

static encode_tiled_fn get_encode_fn() {
    static encode_tiled_fn fn = nullptr;
    if (!fn) {
        void* p = nullptr;
        cudaDriverEntryPointQueryResult qr;
        cudaGetDriverEntryPointByVersion("cuTensorMapEncodeTiled", &p, 12000,
                                         cudaEnableDefault, &qr);
        fn = (encode_tiled_fn)p;
    }
    return fn;
}

extern "C" void kernel_launch(void* const* d_in, const int* in_sizes, int n_in,
                              void* d_out, int out_size) {
    const float* x;
    const float* base;
    if (in_sizes[0] == B_DIM * D_DIM) {
        x = (const float*)d_in[0];
        base = (const float*)d_in[1];
    } else {
        x = (const float*)d_in[1];
        base = (const float*)d_in[0];
    }
    float* out = (float*)d_out;

    // base viewed as 2D: [D*L rows of H floats]; box = [HC, L]
    CUtensorMap tmap;
    memset(&tmap, 0, sizeof(tmap));
    {
        encode_tiled_fn enc = get_encode_fn();
        cuuint64_t dims[2]    = {(cuuint64_t)H_DIM, (cuuint64_t)(D_DIM * L_DIM)};
        cuuint64_t strides[1] = {(cuuint64_t)H_DIM * 4};
        cuuint32_t box[2]     = {HC, L_DIM};
        cuuint32_t estr[2]    = {1, 1};
        enc(&tmap, CU_TENSOR_MAP_DATA_TYPE_FLOAT32, 2, (void*)base,
            dims, strides, box, estr,
            CU_TENSOR_MAP_INTERLEAVE_NONE, CU_TENSOR_MAP_SWIZZLE_NONE,
            CU_TENSOR_MAP_L2_PROMOTION_L2_128B, CU_TENSOR_MAP_FLOAT_OOB_FILL_NONE);
    }

    precomp_kernel<<<(D_DIM * B_DIM + 255) / 256, 256>>>(x);

    encode_kernel<<<GRID, NTHR>>>(tmap, out);

    normalize_kernel<<<B_DIM, 256>>>(out);
}

// round 16
// speedup vs baseline: 1.0598x; 1.0598x over previous
#include <cuda_runtime.h>
#include <cuda.h>
#include <cstdint>
#include <cstddef>
#include <cstring>

#define D_DIM 64
#define L_DIM 100
#define B_DIM 256
#define H_DIM 10000
#define HC    32                 // h-columns per work item
#define PITCH 32                 // floats per tile row (dense, TMA-packed)
#define DPB   16                 // d's per work item (D split 4 ways)
#define NPART 4
#define NSLICE 313               // ceil(H/HC)
#define NWORK (NSLICE * NPART)   // 1252
#define GRID  296                // 148 SM x occ 2: persistent grid
#define NWHOLE (GRID * 4)        // 1184 items assigned whole
#define NHALF  (NWORK - NWHOLE)  // 68 items split into 136 halves (blocks 0..135)
#define TILE_FLOATS (L_DIM * PITCH)
#define TILE_BYTES  (TILE_FLOATS * 4)       // 12800
#define SCR_BYTES   (B_DIM * 8)             // 2048
#define NBUF  6
#define NTHR  512
#define NWARP (NTHR / 32)

// per-(d,b): {off_lo | off_hi<<16, alpha bits}
__device__ uint2 g_scr2[D_DIM * B_DIM];
// partial sums for D-parts 1..3 (part 0 writes d_out directly)
__device__ float g_part[NPART - 1][B_DIM * H_DIM];

__device__ __forceinline__ void griddep_wait() {
    asm volatile("griddepcontrol.wait;" ::: "memory");
}
__device__ __forceinline__ void griddep_launch_dependents() {
    asm volatile("griddepcontrol.launch_dependents;" ::: "memory");
}

__global__ void __launch_bounds__(256) precomp_kernel(const float* __restrict__ x) {
    int idx = blockIdx.x * 256 + threadIdx.x;
    if (idx >= D_DIM * B_DIM) return;
    int d = idx >> 8;
    int b = idx & 255;
    float xv = x[b * D_DIM + d];
    float xn = fminf(fmaxf(xv * (float)(L_DIM - 1), 0.0f), (float)(L_DIM - 1));
    float fl = floorf(xn);
    int lo = (int)fl;
    int hi = min(lo + 1, L_DIM - 1);
    uint2 r;
    r.x = (uint32_t)(lo * PITCH) | ((uint32_t)(hi * PITCH) << 16);
    r.y = __float_as_uint(xn - fl);
    g_scr2[idx] = r;
}

// ---- Blackwell packed fp32x2 helpers ----
__device__ __forceinline__ unsigned long long pk2(float v) {
    unsigned long long r;
    asm("mov.b64 %0, {%1, %2};" : "=l"(r) : "f"(v), "f"(v));
    return r;
}
__device__ __forceinline__ unsigned long long ffma2(unsigned long long a,
                                                    unsigned long long b,
                                                    unsigned long long c) {
    unsigned long long d;
    asm("fma.rn.f32x2 %0, %1, %2, %3;" : "=l"(d) : "l"(a), "l"(b), "l"(c));
    return d;
}

// ---- mbarrier / TMA helpers ----
__device__ __forceinline__ void mbar_init(uint32_t addr, uint32_t count) {
    asm volatile("mbarrier.init.shared.b64 [%0], %1;" :: "r"(addr), "r"(count) : "memory");
}
__device__ __forceinline__ void mbar_expect_tx(uint32_t addr, uint32_t bytes) {
    asm volatile("mbarrier.arrive.expect_tx.shared.b64 _, [%0], %1;"
                 :: "r"(addr), "r"(bytes) : "memory");
}
__device__ __forceinline__ void mbar_arrive(uint32_t addr) {
    asm volatile("mbarrier.arrive.release.cta.shared::cta.b64 _, [%0];"
                 :: "r"(addr) : "memory");
}
__device__ __forceinline__ void mbar_wait_acq(uint32_t addr, uint32_t parity) {
    asm volatile(
        "{\n\t.reg .pred P;\n"
        "WL_%=:\n\t"
        "mbarrier.try_wait.parity.acquire.cta.shared::cta.b64 P, [%0], %1, 0x989680;\n\t"
        "@!P bra WL_%=;\n\t}"
        :: "r"(addr), "r"(parity) : "memory");
}
__device__ __forceinline__ void tma_load_2d(uint32_t smem_dst, const CUtensorMap* tmap,
                                            int cx, int cy, uint32_t mbar) {
    asm volatile(
        "cp.async.bulk.tensor.2d.shared::cta.global.tile.mbarrier::complete_tx::bytes "
        "[%0], [%1, {%2, %3}], [%4];"
        :: "r"(smem_dst), "l"(tmap), "r"(cx), "r"(cy), "r"(mbar) : "memory");
}
__device__ __forceinline__ void bulk_copy_g2s(uint32_t smem_dst, const void* gsrc,
                                              uint32_t bytes, uint32_t mbar) {
    unsigned long long ga = (unsigned long long)__cvta_generic_to_global(gsrc);
    asm volatile(
        "cp.async.bulk.shared::cta.global.mbarrier::complete_tx::bytes [%0], [%1], %2, [%3];"
        :: "r"(smem_dst), "l"(ga), "r"(bytes), "r"(mbar) : "memory");
}

// item id for local unit wi of block bid (wi<4 whole; wi==4 = half item)
__device__ __forceinline__ int unit_item(int bid, int wi) {
    return (wi < 4) ? (bid + wi * GRID) : (NWHOLE + (bid >> 1));
}

__global__ void __launch_bounds__(NTHR, 2) encode_kernel(
        const __grid_constant__ CUtensorMap tmap,
        float* __restrict__ out) {
    __shared__ float tile[NBUF][TILE_FLOATS];
    __shared__ uint2 sscr[NBUF][B_DIM];
    __shared__ __align__(8) unsigned long long mb_full[NBUF];
    __shared__ __align__(8) unsigned long long mb_empty[NBUF];

    const int tid  = threadIdx.x;
    const int lane = tid & 31;
    const int wrp  = tid >> 5;
    const int hg   = tid & 7;        // which float4 within the 32-column slice
    const int bg   = tid >> 3;       // batch group: 4 batches per thread (0..63)
    const int bid  = blockIdx.x;

    // blocks 0..135 get 4 whole items + 1 half item; blocks 136..295 get 4
    const int nitems  = (bid < NHALF * 2) ? 5 : 4;
    const int nstages = nitems * DPB;
    const int hsel    = bid & 1;     // which batch half for the half item

    if (tid == 0) {
#pragma unroll
        for (int i = 0; i < NBUF; ++i) {
            mbar_init((uint32_t)__cvta_generic_to_shared(&mb_full[i]), 1);
            mbar_init((uint32_t)__cvta_generic_to_shared(&mb_empty[i]), NWARP);
        }
        asm volatile("fence.proxy.async.shared::cta;" ::: "memory");
    }
    __syncthreads();          // the only block-wide barrier

    // PDL: prologue above is independent of precomp's output; wait here
    // before the first g_scr2 access (in issue()).
    griddep_wait();

    // producer: issue local stage ls (unit wi = ls/16, t = ls%16)
    auto issue = [&](int ls) {
        int wi = ls >> 4;
        int t  = ls & 15;
        int w  = unit_item(bid, wi);
        int part  = w & 3;
        int slice = w >> 2;
        int d     = part * DPB + t;
        int slot  = ls % NBUF;
        uint32_t bar = (uint32_t)__cvta_generic_to_shared(&mb_full[slot]);
        mbar_expect_tx(bar, TILE_BYTES + SCR_BYTES);
        tma_load_2d((uint32_t)__cvta_generic_to_shared(&tile[slot][0]),
                    &tmap, slice * HC, d * L_DIM, bar);
        bulk_copy_g2s((uint32_t)__cvta_generic_to_shared(&sscr[slot][0]),
                      &g_scr2[d * B_DIM], SCR_BYTES, bar);
    };

    if (tid == 0) {
        int npro = (nstages < NBUF - 1) ? nstages : (NBUF - 1);
        for (int ls = 0; ls < npro; ++ls) issue(ls);
    }

    int ls = 0;
    for (int wi = 0; wi < nitems; ++wi) {
        const int w      = unit_item(bid, wi);
        const int part   = w & 3;
        const int slice  = w >> 2;
        const int h      = slice * HC + hg * 4;
        const bool active = (wi < 4) || ((bg >> 5) == hsel);   // half item: my batch half?
        const bool do_out = active && (h < H_DIM);
        float* dst = (part == 0) ? out : &g_part[part - 1][0];

        unsigned long long acc[4][2];
#pragma unroll
        for (int i = 0; i < 4; ++i) { acc[i][0] = 0ull; acc[i][1] = 0ull; }

        for (int t = 0; t < DPB; ++t, ++ls) {
            const int slot = ls % NBUF;
            mbar_wait_acq((uint32_t)__cvta_generic_to_shared(&mb_full[slot]),
                          (uint32_t)((ls / NBUF) & 1));

            if (active) {
                const float* tb = tile[slot];
                const uint2* sc = &sscr[slot][bg * 4];
#pragma unroll
                for (int i = 0; i < 4; ++i) {
                    uint2 s = sc[i];                // LDS.64 broadcast within 8-lane group
                    int off_lo = (int)(s.x & 0xFFFFu);
                    int off_hi = (int)(s.x >> 16);
                    float a = __uint_as_float(s.y);
                    unsigned long long wa = pk2(a);
                    unsigned long long w0 = pk2(1.0f - a);
                    ulonglong2 vl = *reinterpret_cast<const ulonglong2*>(tb + off_lo + hg * 4);
                    ulonglong2 vh = *reinterpret_cast<const ulonglong2*>(tb + off_hi + hg * 4);
                    acc[i][0] = ffma2(w0, vl.x, acc[i][0]);
                    acc[i][1] = ffma2(w0, vl.y, acc[i][1]);
                    acc[i][0] = ffma2(wa, vh.x, acc[i][0]);
                    acc[i][1] = ffma2(wa, vh.y, acc[i][1]);
                }
            }

            __syncwarp();
            if (lane == 0)
                mbar_arrive((uint32_t)__cvta_generic_to_shared(&mb_empty[slot]));

            // rotating producer: stage ln is issued by warp (ln & 15)
            {
                int ln = ls + NBUF - 1;
                if (ln < nstages && wrp == (ln & 15) && lane == 0) {
                    int j = ln / NBUF;          // reuse index of that slot
                    if (j >= 1)
                        mbar_wait_acq((uint32_t)__cvta_generic_to_shared(&mb_empty[ln % NBUF]),
                                      (uint32_t)((j - 1) & 1));
                    issue(ln);
                }
            }
        }

        if (do_out) {
#pragma unroll
            for (int i = 0; i < 4; ++i) {
                ulonglong2 o;
                o.x = acc[i][0];
                o.y = acc[i][1];
                *reinterpret_cast<ulonglong2*>(dst + (size_t)(bg * 4 + i) * H_DIM + h) = o;
            }
        }
    }
}

__global__ void __launch_bounds__(256) normalize_kernel(float* __restrict__ out) {
    // PDL: nothing useful to do before encode's output is ready
    griddep_wait();

    int b = blockIdx.x;
    const size_t off = (size_t)b * H_DIM;
    float* row = out + off;
    const float* p0 = &g_part[0][off];
    const float* p1 = &g_part[1][off];
    const float* p2 = &g_part[2][off];

    float ss = 0.0f;
    for (int i = threadIdx.x * 4; i < H_DIM; i += 256 * 4) {
        float4 v  = *reinterpret_cast<const float4*>(row + i);
        float4 a0 = *reinterpret_cast<const float4*>(p0 + i);
        float4 a1 = *reinterpret_cast<const float4*>(p1 + i);
        float4 a2 = *reinterpret_cast<const float4*>(p2 + i);
        v.x += a0.x + a1.x + a2.x;
        v.y += a0.y + a1.y + a2.y;
        v.z += a0.z + a1.z + a2.z;
        v.w += a0.w + a1.w + a2.w;
        *reinterpret_cast<float4*>(row + i) = v;    // store combined (pre-norm)
        ss += v.x * v.x + v.y * v.y + v.z * v.z + v.w * v.w;
    }
#pragma unroll
    for (int o = 16; o; o >>= 1) ss += __shfl_down_sync(0xffffffffu, ss, o);

    __shared__ float red[8];
    __shared__ float inv_s;
    if ((threadIdx.x & 31) == 0) red[threadIdx.x >> 5] = ss;
    __syncthreads();
    if (threadIdx.x == 0) {
        float t = 0.0f;
#pragma unroll
        for (int i = 0; i < 8; ++i) t += red[i];
        inv_s = rsqrtf(t);
    }
    __syncthreads();
    float inv = inv_s;

    for (int i = threadIdx.x * 4; i < H_DIM; i += 256 * 4) {
        float4 v = *reinterpret_cast<const float4*>(row + i);
        v.x *= inv; v.y *= inv; v.z *= inv; v.w *= inv;
        *reinterpret_cast<float4*>(row + i) = v;
    }
}

// ---- host-side tensor-map construction (no -lcuda needed) ----
typedef CUresult (*encode_tiled_fn)(
    CUtensorMap*, CUtensorMapDataType, cuuint32_t, void*,
    const cuuint64_t*, const cuuint64_t*, const cuuint32_t*, const cuuint32_t*,
    CUtensorMapInterleave, CUtensorMapSwizzle, CUtensorMapL2promotion,
    CUtensorMapFloatOOBfill);

static encode_tiled_fn get_encode_fn() {
    static encode_tiled_fn fn = nullptr;
    if (!fn) {
        void* p = nullptr;
        cudaDriverEntryPointQueryResult qr;
        cudaGetDriverEntryPointByVersion("cuTensorMapEncodeTiled", &p, 12000,
                                         cudaEnableDefault, &qr);
        fn = (encode_tiled_fn)p;
    }
    return fn;
}

extern "C" void kernel_launch(void* const* d_in, const int* in_sizes, int n_in,
                              void* d_out, int out_size) {
    const float* x;
    const float* base;
    if (in_sizes[0] == B_DIM * D_DIM) {
        x = (const float*)d_in[0];
        base = (const float*)d_in[1];
    } else {
        x = (const float*)d_in[1];
        base = (const float*)d_in[0];
    }
    float* out = (float*)d_out;

    // base viewed as 2D: [D*L rows of H floats]; box = [HC, L]
    CUtensorMap tmap;
    memset(&tmap, 0, sizeof(tmap));
    {
        encode_tiled_fn enc = get_encode_fn();
        cuuint64_t dims[2]    = {(cuuint64_t)H_DIM, (cuuint64_t)(D_DIM * L_DIM)};
        cuuint64_t strides[1] = {(cuuint64_t)H_DIM * 4};
        cuuint32_t box[2]     = {HC, L_DIM};
        cuuint32_t estr[2]    = {1, 1};
        enc(&tmap, CU_TENSOR_MAP_DATA_TYPE_FLOAT32, 2, (void*)base,
            dims, strides, box, estr,
            CU_TENSOR_MAP_INTERLEAVE_NONE, CU_TENSOR_MAP_SWIZZLE_NONE,
            CU_TENSOR_MAP_L2_PROMOTION_L2_128B, CU_TENSOR_MAP_FLOAT_OOB_FILL_NONE);
    }

    precomp_kernel<<<(D_DIM * B_DIM + 255) / 256, 256>>>(x);

    // encode: PDL launch — overlaps its prologue with precomp's tail
    {
        cudaLaunchConfig_t cfg = {};
        cfg.gridDim  = {GRID, 1, 1};
        cfg.blockDim = {NTHR, 1, 1};
        cudaLaunchAttribute attr[1];
        attr[0].id = cudaLaunchAttributeProgrammaticStreamSerialization;
        attr[0].val.programmaticStreamSerializationAllowed = 1;
        cfg.attrs = attr;
        cfg.numAttrs = 1;
        cudaLaunchKernelEx(&cfg, encode_kernel, tmap, out);
    }

    // normalize: PDL launch — overlaps launch setup with encode's tail
    {
        cudaLaunchConfig_t cfg = {};
        cfg.gridDim  = {B_DIM, 1, 1};
        cfg.blockDim = {256, 1, 1};
        cudaLaunchAttribute attr[1];
        attr[0].id = cudaLaunchAttributeProgrammaticStreamSerialization;
        attr[0].val.programmaticStreamSerializationAllowed = 1;
        cfg.attrs = attr;
        cfg.numAttrs = 1;
        cudaLaunchKernelEx(&cfg, normalize_kernel, out);
    }
}

// round 17
// speedup vs baseline: 1.0618x; 1.0019x over previous
#include <cuda_runtime.h>
#include <cuda.h>
#include <cstdint>
#include <cstddef>
#include <cstring>

#define D_DIM 64
#define L_DIM 100
#define B_DIM 256
#define H_DIM 10000
#define HC    32                 // h-columns per work item
#define PITCH 32                 // floats per tile row (dense, TMA-packed)
#define DPB   16                 // d's per work item (D split 4 ways)
#define NPART 4
#define NSLICE 313               // ceil(H/HC)
#define NWORK (NSLICE * NPART)   // 1252
#define GRID  296                // 148 SM x occ 2: persistent grid
#define NWHOLE (GRID * 4)        // 1184 items assigned whole
#define NHALF  (NWORK - NWHOLE)  // 68 items split into 136 halves (blocks 0..135)
#define TILE_FLOATS (L_DIM * PITCH)
#define TILE_BYTES  (TILE_FLOATS * 4)       // 12800
#define SCR_BYTES   (B_DIM * 8)             // 2048
#define NBUF  6
#define NTHR  512
#define NWARP (NTHR / 32)

// per-(d,b): {off_lo | off_hi<<16, alpha bits}
__device__ uint2 g_scr2[D_DIM * B_DIM];
// partial sums for D-parts 1..3 (part 0 writes d_out directly)
__device__ float g_part[NPART - 1][B_DIM * H_DIM];

__device__ __forceinline__ void griddep_wait() {
    asm volatile("griddepcontrol.wait;" ::: "memory");
}
__device__ __forceinline__ void griddep_launch_dependents() {
    asm volatile("griddepcontrol.launch_dependents;" ::: "memory");
}

__global__ void __launch_bounds__(256) precomp_kernel(const float* __restrict__ x) {
    int idx = blockIdx.x * 256 + threadIdx.x;
    if (idx < D_DIM * B_DIM) {
        int d = idx >> 8;
        int b = idx & 255;
        float xv = x[b * D_DIM + d];
        float xn = fminf(fmaxf(xv * (float)(L_DIM - 1), 0.0f), (float)(L_DIM - 1));
        float fl = floorf(xn);
        int lo = (int)fl;
        int hi = min(lo + 1, L_DIM - 1);
        uint2 r;
        r.x = (uint32_t)(lo * PITCH) | ((uint32_t)(hi * PITCH) << 16);
        r.y = __float_as_uint(xn - fl);
        g_scr2[idx] = r;
    }
    __syncthreads();                    // all stores in this CTA done
    griddep_launch_dependents();        // release encode before kernel teardown
}

// ---- Blackwell packed fp32x2 helpers ----
__device__ __forceinline__ unsigned long long pk2(float v) {
    unsigned long long r;
    asm("mov.b64 %0, {%1, %2};" : "=l"(r) : "f"(v), "f"(v));
    return r;
}
__device__ __forceinline__ unsigned long long ffma2(unsigned long long a,
                                                    unsigned long long b,
                                                    unsigned long long c) {
    unsigned long long d;
    asm("fma.rn.f32x2 %0, %1, %2, %3;" : "=l"(d) : "l"(a), "l"(b), "l"(c));
    return d;
}

// ---- mbarrier / TMA helpers ----
__device__ __forceinline__ void mbar_init(uint32_t addr, uint32_t count) {
    asm volatile("mbarrier.init.shared.b64 [%0], %1;" :: "r"(addr), "r"(count) : "memory");
}
__device__ __forceinline__ void mbar_expect_tx(uint32_t addr, uint32_t bytes) {
    asm volatile("mbarrier.arrive.expect_tx.shared.b64 _, [%0], %1;"
                 :: "r"(addr), "r"(bytes) : "memory");
}
__device__ __forceinline__ void mbar_arrive(uint32_t addr) {
    asm volatile("mbarrier.arrive.release.cta.shared::cta.b64 _, [%0];"
                 :: "r"(addr) : "memory");
}
__device__ __forceinline__ void mbar_wait_acq(uint32_t addr, uint32_t parity) {
    asm volatile(
        "{\n\t.reg .pred P;\n"
        "WL_%=:\n\t"
        "mbarrier.try_wait.parity.acquire.cta.shared::cta.b64 P, [%0], %1, 0x989680;\n\t"
        "@!P bra WL_%=;\n\t}"
        :: "r"(addr), "r"(parity) : "memory");
}
__device__ __forceinline__ void tma_load_2d(uint32_t smem_dst, const CUtensorMap* tmap,
                                            int cx, int cy, uint32_t mbar) {
    asm volatile(
        "cp.async.bulk.tensor.2d.shared::cta.global.tile.mbarrier::complete_tx::bytes "
        "[%0], [%1, {%2, %3}], [%4];"
        :: "r"(smem_dst), "l"(tmap), "r"(cx), "r"(cy), "r"(mbar) : "memory");
}
__device__ __forceinline__ void bulk_copy_g2s(uint32_t smem_dst, const void* gsrc,
                                              uint32_t bytes, uint32_t mbar) {
    unsigned long long ga = (unsigned long long)__cvta_generic_to_global(gsrc);
    asm volatile(
        "cp.async.bulk.shared::cta.global.mbarrier::complete_tx::bytes [%0], [%1], %2, [%3];"
        :: "r"(smem_dst), "l"(ga), "r"(bytes), "r"(mbar) : "memory");
}

// item id for local unit wi of block bid (wi<4 whole; wi==4 = half item)
__device__ __forceinline__ int unit_item(int bid, int wi) {
    return (wi < 4) ? (bid + wi * GRID) : (NWHOLE + (bid >> 1));
}

__global__ void __launch_bounds__(NTHR, 2) encode_kernel(
        const __grid_constant__ CUtensorMap tmap,
        float* __restrict__ out) {
    __shared__ float tile[NBUF][TILE_FLOATS];
    __shared__ uint2 sscr[NBUF][B_DIM];
    __shared__ __align__(8) unsigned long long mb_full[NBUF];
    __shared__ __align__(8) unsigned long long mb_empty[NBUF];

    const int tid  = threadIdx.x;
    const int lane = tid & 31;
    const int wrp  = tid >> 5;
    const int hg   = tid & 7;        // which float4 within the 32-column slice
    const int bg   = tid >> 3;       // batch group: 4 batches per thread (0..63)
    const int bid  = blockIdx.x;

    // blocks 0..135 get 4 whole items + 1 half item; blocks 136..295 get 4
    const int nitems  = (bid < NHALF * 2) ? 5 : 4;
    const int nstages = nitems * DPB;
    const int hsel    = bid & 1;     // which batch half for the half item

    if (tid == 0) {
#pragma unroll
        for (int i = 0; i < NBUF; ++i) {
            mbar_init((uint32_t)__cvta_generic_to_shared(&mb_full[i]), 1);
            mbar_init((uint32_t)__cvta_generic_to_shared(&mb_empty[i]), NWARP);
        }
        asm volatile("fence.proxy.async.shared::cta;" ::: "memory");
    }
    __syncthreads();          // the only block-wide barrier

    // PDL: prologue above is independent of precomp's output; wait here
    // before the first g_scr2 access (in issue()).
    griddep_wait();

    // producer: issue local stage ls (unit wi = ls/16, t = ls%16)
    auto issue = [&](int ls) {
        int wi = ls >> 4;
        int t  = ls & 15;
        int w  = unit_item(bid, wi);
        int part  = w & 3;
        int slice = w >> 2;
        int d     = part * DPB + t;
        int slot  = ls % NBUF;
        uint32_t bar = (uint32_t)__cvta_generic_to_shared(&mb_full[slot]);
        mbar_expect_tx(bar, TILE_BYTES + SCR_BYTES);
        tma_load_2d((uint32_t)__cvta_generic_to_shared(&tile[slot][0]),
                    &tmap, slice * HC, d * L_DIM, bar);
        bulk_copy_g2s((uint32_t)__cvta_generic_to_shared(&sscr[slot][0]),
                      &g_scr2[d * B_DIM], SCR_BYTES, bar);
    };

    if (tid == 0) {
        int npro = (nstages < NBUF - 1) ? nstages : (NBUF - 1);
        for (int ls = 0; ls < npro; ++ls) issue(ls);
    }

    int ls = 0;
    for (int wi = 0; wi < nitems; ++wi) {
        const int w      = unit_item(bid, wi);
        const int part   = w & 3;
        const int slice  = w >> 2;
        const int h      = slice * HC + hg * 4;
        const bool active = (wi < 4) || ((bg >> 5) == hsel);   // half item: my batch half?
        const bool do_out = active && (h < H_DIM);
        float* dst = (part == 0) ? out : &g_part[part - 1][0];

        unsigned long long acc[4][2];
#pragma unroll
        for (int i = 0; i < 4; ++i) { acc[i][0] = 0ull; acc[i][1] = 0ull; }

        for (int t = 0; t < DPB; ++t, ++ls) {
            const int slot = ls % NBUF;
            mbar_wait_acq((uint32_t)__cvta_generic_to_shared(&mb_full[slot]),
                          (uint32_t)((ls / NBUF) & 1));

            if (active) {
                const float* tb = tile[slot];
                const uint2* sc = &sscr[slot][bg * 4];
#pragma unroll
                for (int i = 0; i < 4; ++i) {
                    uint2 s = sc[i];                // LDS.64 broadcast within 8-lane group
                    int off_lo = (int)(s.x & 0xFFFFu);
                    int off_hi = (int)(s.x >> 16);
                    float a = __uint_as_float(s.y);
                    unsigned long long wa = pk2(a);
                    unsigned long long w0 = pk2(1.0f - a);
                    ulonglong2 vl = *reinterpret_cast<const ulonglong2*>(tb + off_lo + hg * 4);
                    ulonglong2 vh = *reinterpret_cast<const ulonglong2*>(tb + off_hi + hg * 4);
                    acc[i][0] = ffma2(w0, vl.x, acc[i][0]);
                    acc[i][1] = ffma2(w0, vl.y, acc[i][1]);
                    acc[i][0] = ffma2(wa, vh.x, acc[i][0]);
                    acc[i][1] = ffma2(wa, vh.y, acc[i][1]);
                }
            }

            __syncwarp();
            if (lane == 0)
                mbar_arrive((uint32_t)__cvta_generic_to_shared(&mb_empty[slot]));

            // rotating producer: stage ln is issued by warp (ln & 15)
            {
                int ln = ls + NBUF - 1;
                if (ln < nstages && wrp == (ln & 15) && lane == 0) {
                    int j = ln / NBUF;          // reuse index of that slot
                    if (j >= 1)
                        mbar_wait_acq((uint32_t)__cvta_generic_to_shared(&mb_empty[ln % NBUF]),
                                      (uint32_t)((j - 1) & 1));
                    issue(ln);
                }
            }
        }

        if (do_out) {
#pragma unroll
            for (int i = 0; i < 4; ++i) {
                ulonglong2 o;
                o.x = acc[i][0];
                o.y = acc[i][1];
                *reinterpret_cast<ulonglong2*>(dst + (size_t)(bg * 4 + i) * H_DIM + h) = o;
            }
        }
    }

    // all of this block's output stores are issued; let normalize ramp up
    griddep_launch_dependents();
}

__global__ void __launch_bounds__(256) normalize_kernel(float* __restrict__ out) {
    __shared__ float srow[H_DIM];       // 40 KB: combined row staging
    __shared__ float red[8];
    __shared__ float inv_s;

    // PDL: nothing useful to do before encode's output is ready
    griddep_wait();

    int b = blockIdx.x;
    const size_t off = (size_t)b * H_DIM;
    float* row = out + off;
    const float* p0 = &g_part[0][off];
    const float* p1 = &g_part[1][off];
    const float* p2 = &g_part[2][off];

    float ss = 0.0f;
    for (int i = threadIdx.x * 4; i < H_DIM; i += 256 * 4) {
        float4 v  = *reinterpret_cast<const float4*>(row + i);
        float4 a0 = *reinterpret_cast<const float4*>(p0 + i);
        float4 a1 = *reinterpret_cast<const float4*>(p1 + i);
        float4 a2 = *reinterpret_cast<const float4*>(p2 + i);
        v.x += a0.x + a1.x + a2.x;
        v.y += a0.y + a1.y + a2.y;
        v.z += a0.z + a1.z + a2.z;
        v.w += a0.w + a1.w + a2.w;
        *reinterpret_cast<float4*>(&srow[i]) = v;   // stage combined in smem
        ss += v.x * v.x + v.y * v.y + v.z * v.z + v.w * v.w;
    }
#pragma unroll
    for (int o = 16; o; o >>= 1) ss += __shfl_down_sync(0xffffffffu, ss, o);

    if ((threadIdx.x & 31) == 0) red[threadIdx.x >> 5] = ss;
    __syncthreads();
    if (threadIdx.x == 0) {
        float t = 0.0f;
#pragma unroll
        for (int i = 0; i < 8; ++i) t += red[i];
        inv_s = rsqrtf(t);
    }
    __syncthreads();
    float inv = inv_s;

    for (int i = threadIdx.x * 4; i < H_DIM; i += 256 * 4) {
        float4 v = *reinterpret_cast<const float4*>(&srow[i]);
        v.x *= inv; v.y *= inv; v.z *= inv; v.w *= inv;
        *reinterpret_cast<float4*>(row + i) = v;    // single gmem store
    }
}

// ---- host-side tensor-map construction (no -lcuda needed) ----
typedef CUresult (*encode_tiled_fn)(
    CUtensorMap*, CUtensorMapDataType, cuuint32_t, void*,
    const cuuint64_t*, const cuuint64_t*, const cuuint32_t*, const cuuint32_t*,
    CUtensorMapInterleave, CUtensorMapSwizzle, CUtensorMapL2promotion,
    CUtensorMapFloatOOBfill);

static encode_tiled_fn get_encode_fn() {
    static encode_tiled_fn fn = nullptr;
    if (!fn) {
        void* p = nullptr;
        cudaDriverEntryPointQueryResult qr;
        cudaGetDriverEntryPointByVersion("cuTensorMapEncodeTiled", &p, 12000,
                                         cudaEnableDefault, &qr);
        fn = (encode_tiled_fn)p;
    }
    return fn;
}

extern "C" void kernel_launch(void* const* d_in, const int* in_sizes, int n_in,
                              void* d_out, int out_size) {
    const float* x;
    const float* base;
    if (in_sizes[0] == B_DIM * D_DIM) {
        x = (const float*)d_in[0];
        base = (const float*)d_in[1];
    } else {
        x = (const float*)d_in[1];
        base = (const float*)d_in[0];
    }
    float* out = (float*)d_out;

    // base viewed as 2D: [D*L rows of H floats]; box = [HC, L]
    CUtensorMap tmap;
    memset(&tmap, 0, sizeof(tmap));
    {
        encode_tiled_fn enc = get_encode_fn();
        cuuint64_t dims[2]    = {(cuuint64_t)H_DIM, (cuuint64_t)(D_DIM * L_DIM)};
        cuuint64_t strides[1] = {(cuuint64_t)H_DIM * 4};
        cuuint32_t box[2]     = {HC, L_DIM};
        cuuint32_t estr[2]    = {1, 1};
        enc(&tmap, CU_TENSOR_MAP_DATA_TYPE_FLOAT32, 2, (void*)base,
            dims, strides, box, estr,
            CU_TENSOR_MAP_INTERLEAVE_NONE, CU_TENSOR_MAP_SWIZZLE_NONE,
            CU_TENSOR_MAP_L2_PROMOTION_L2_128B, CU_TENSOR_MAP_FLOAT_OOB_FILL_NONE);
    }

    precomp_kernel<<<(D_DIM * B_DIM + 255) / 256, 256>>>(x);

    // encode: PDL launch — overlaps its prologue with precomp's tail
    {
        cudaLaunchConfig_t cfg = {};
        cfg.gridDim  = {GRID, 1, 1};
        cfg.blockDim = {NTHR, 1, 1};
        cudaLaunchAttribute attr[1];
        attr[0].id = cudaLaunchAttributeProgrammaticStreamSerialization;
        attr[0].val.programmaticStreamSerializationAllowed = 1;
        cfg.attrs = attr;
        cfg.numAttrs = 1;
        cudaLaunchKernelEx(&cfg, encode_kernel, tmap, out);
    }

    // normalize: PDL launch — overlaps launch setup with encode's tail
    {
        cudaLaunchConfig_t cfg = {};
        cfg.gridDim  = {B_DIM, 1, 1};
        cfg.blockDim = {256, 1, 1};
        cudaLaunchAttribute attr[1];
        attr[0].id = cudaLaunchAttributeProgrammaticStreamSerialization;
        attr[0].val.programmaticStreamSerializationAllowed = 1;
        cfg.attrs = attr;
        cfg.numAttrs = 1;
        cudaLaunchKernelEx(&cfg, normalize_kernel, out);
    }
}